// round 9
// baseline (speedup 1.0000x reference)
#include <cuda_runtime.h>
#include <cuda_bf16.h>

// AttWModel — N=1024, L=2048, D=128
// out[n] = sum_l softmax_l( X[n,l]·q[n] ) * ( X[n,l]·v ),  q[n] = W^T z[n]
//
// R9: R8 stream/finalize unchanged; q-kernel rebuilt as register-blocked
// (2 n x 4 d per thread), W streamed through L1 (no smem staging).

#define NB    1024
#define LSEQ  2048
#define DIM   128
#define NW    8
#define NBLK  1184

__device__ float  g_q[NB * DIM];
__device__ float4 g_part[NBLK];     // {Za, Na, Zb, Nb}

// ---------------------------------------------------------------------------
// Kernel 1: q = W^T z. 128 blocks x 128 threads; block owns 8 n's.
// Thread (wid, d4): accumulates q[n0+2*wid+{0,1}][4*d4..4*d4+3].
// Per e-iter: 1 coalesced LDG.128 of W row chunk (L1-resident), 2 LDS
// broadcasts of z, 8 FMA. No W smem -> no crossbar bottleneck.
// ---------------------------------------------------------------------------
__global__ void __launch_bounds__(128) compute_q_kernel(
    const float* __restrict__ z, const float* __restrict__ W)
{
    __shared__ __align__(16) float zs[8 * DIM];   // 4 KB

    const int tid = threadIdx.x;
    const int n0  = blockIdx.x * 8;

    // stage 8 z rows (1024 floats over 128 threads, float4-coalesced)
#pragma unroll
    for (int k = 0; k < 2; k++) {
        const int idx = k * 128 + tid;
        reinterpret_cast<float4*>(zs)[idx] =
            reinterpret_cast<const float4*>(z + n0 * DIM)[idx];
    }
    __syncthreads();

    const int d4  = tid & 31;          // float4 column group
    const int wid = tid >> 5;          // 0..3 -> n pair

    const float* z0 = zs + (2 * wid)     * DIM;
    const float* z1 = zs + (2 * wid + 1) * DIM;
    const float4* Wp = reinterpret_cast<const float4*>(W) + d4;

    float4 a0 = make_float4(0.f, 0.f, 0.f, 0.f);
    float4 a1 = make_float4(0.f, 0.f, 0.f, 0.f);

#pragma unroll 8
    for (int e = 0; e < DIM; e++) {
        const float4 w = Wp[e * 32];
        const float f0 = z0[e];
        const float f1 = z1[e];
        a0.x = fmaf(f0, w.x, a0.x);  a0.y = fmaf(f0, w.y, a0.y);
        a0.z = fmaf(f0, w.z, a0.z);  a0.w = fmaf(f0, w.w, a0.w);
        a1.x = fmaf(f1, w.x, a1.x);  a1.y = fmaf(f1, w.y, a1.y);
        a1.z = fmaf(f1, w.z, a1.z);  a1.w = fmaf(f1, w.w, a1.w);
    }

    reinterpret_cast<float4*>(g_q + (n0 + 2 * wid)     * DIM)[d4] = a0;
    reinterpret_cast<float4*>(g_q + (n0 + 2 * wid + 1) * DIM)[d4] = a1;
}

// ---------------------------------------------------------------------------
// Phase worker: rows [r0, r1) of the flattened space, fixed n. (unchanged R8)
// ---------------------------------------------------------------------------
__device__ __forceinline__ void phase_loop(
    const float4* __restrict__ Xf,
    int r0, int r1, int wid, int lane,
    float4 q4, float4 v4, float& Z, float& num)
{
    int j = r0 + wid;
    const float4* p = Xf + (size_t)j * 32 + lane;

#pragma unroll 1
    for (; j + NW < r1; j += 2 * NW, p += 2 * NW * 32) {
        const float4 x0 = __ldcs(p);
        const float4 x1 = __ldcs(p + NW * 32);

        float s0 = x0.x*q4.x + x0.y*q4.y + x0.z*q4.z + x0.w*q4.w;
        float t0 = x0.x*v4.x + x0.y*v4.y + x0.z*v4.z + x0.w*v4.w;
        float s1 = x1.x*q4.x + x1.y*q4.y + x1.z*q4.z + x1.w*q4.w;
        float t1 = x1.x*v4.x + x1.y*v4.y + x1.z*v4.z + x1.w*v4.w;

#pragma unroll
        for (int off = 16; off > 0; off >>= 1) {
            s0 += __shfl_xor_sync(0xffffffffu, s0, off);
            s1 += __shfl_xor_sync(0xffffffffu, s1, off);
        }

        const float p0 = __expf(s0);
        const float p1 = __expf(s1);
        Z   += p0 + p1;
        num  = fmaf(p0, t0, fmaf(p1, t1, num));
    }
    if (j < r1) {
        const float4 x0 = __ldcs(p);
        float s0 = x0.x*q4.x + x0.y*q4.y + x0.z*q4.z + x0.w*q4.w;
        float t0 = x0.x*v4.x + x0.y*v4.y + x0.z*v4.z + x0.w*v4.w;
#pragma unroll
        for (int off = 16; off > 0; off >>= 1)
            s0 += __shfl_xor_sync(0xffffffffu, s0, off);
        const float p0 = __expf(s0);
        Z   += p0;
        num  = fmaf(p0, t0, num);
    }
}

// ---------------------------------------------------------------------------
// Kernel 2: streaming (unchanged R8). Block b: rows [b*65536/37, ...).
// ---------------------------------------------------------------------------
__global__ void __launch_bounds__(NW * 32, 8) attw_stream_kernel(
    const float* __restrict__ X,
    const float* __restrict__ v)
{
    const int bid  = blockIdx.x;
    const int lane = threadIdx.x & 31;
    const int wid  = threadIdx.x >> 5;

    const unsigned R0 = ((unsigned)bid << 16) / 37u;
    const unsigned R1 = (((unsigned)bid + 1u) << 16) / 37u;
    const int n0   = (int)(R0 >> 11);
    const int bRow = (int)min(R1, (unsigned)(n0 + 1) << 11);

    const float4* Xf = reinterpret_cast<const float4*>(X);
    const float4  v4 = reinterpret_cast<const float4*>(v)[lane];

    __shared__ float sZa[NW], sNa[NW], sZb[NW], sNb[NW];

    {
        const float4 q4 = reinterpret_cast<const float4*>(g_q + n0 * DIM)[lane];
        float Z = 0.f, num = 0.f;
        phase_loop(Xf, (int)R0, bRow, wid, lane, q4, v4, Z, num);
#pragma unroll
        for (int off = 16; off > 0; off >>= 1)
            num += __shfl_xor_sync(0xffffffffu, num, off);
        if (lane == 0) { sZa[wid] = Z; sNa[wid] = num; }
    }

    {
        float Z = 0.f, num = 0.f;
        if (bRow < (int)R1) {
            const float4 q4 =
                reinterpret_cast<const float4*>(g_q + (n0 + 1) * DIM)[lane];
            phase_loop(Xf, bRow, (int)R1, wid, lane, q4, v4, Z, num);
#pragma unroll
            for (int off = 16; off > 0; off >>= 1)
                num += __shfl_xor_sync(0xffffffffu, num, off);
        }
        if (lane == 0) { sZb[wid] = Z; sNb[wid] = num; }
    }

    __syncthreads();

    if (threadIdx.x == 0) {
        float Za = 0.f, Na = 0.f, Zb = 0.f, Nb = 0.f;
#pragma unroll
        for (int w = 0; w < NW; w++) {
            Za += sZa[w]; Na += sNa[w];
            Zb += sZb[w]; Nb += sNb[w];
        }
        g_part[bid] = make_float4(Za, Na, Zb, Nb);
    }
}

// ---------------------------------------------------------------------------
// Kernel 3: finalize (unchanged R8).
// ---------------------------------------------------------------------------
__global__ void __launch_bounds__(256) finalize_kernel(float* __restrict__ out)
{
    const int n = blockIdx.x * 256 + threadIdx.x;
    if (n >= NB) return;

    const unsigned rlo = (unsigned)n << 11;
    const unsigned rhi = ((unsigned)(n + 1) << 11) - 1u;
    const unsigned bs  = (37u * rlo + 36u) >> 16;
    const unsigned be  = (37u * rhi + 36u) >> 16;

    float Zt = 0.f, Nt = 0.f;
    for (unsigned b = bs; b <= be; b++) {
        const int n0b = (int)(((b << 16) / 37u) >> 11);
        const float4 pw = g_part[b];
        if (n0b == n)          { Zt += pw.x; Nt += pw.y; }
        else if (n0b + 1 == n) { Zt += pw.z; Nt += pw.w; }
    }
    out[n] = Nt / Zt;
}

extern "C" void kernel_launch(void* const* d_in, const int* in_sizes, int n_in,
                              void* d_out, int out_size)
{
    const float* X = (const float*)d_in[0];
    const float* z = (const float*)d_in[1];
    const float* W = (const float*)d_in[2];
    const float* v = (const float*)d_in[3];
    float* out = (float*)d_out;

    compute_q_kernel<<<NB / 8, 128>>>(z, W);
    attw_stream_kernel<<<NBLK, NW * 32>>>(X, v);
    finalize_kernel<<<(NB + 255) / 256, 256>>>(out);
}